// round 14
// baseline (speedup 1.0000x reference)
#include <cuda_runtime.h>

// P1 vector FEM eval on structured 16x16 triangulated unit square.
// Bit-faithful numerics (R4): exact fp32 classification, interior-gridline
// bbox exclusion, argmax tie -> upper triangle, reference op-order output.
//
// FINAL (converged optimum; harness 6.624us reproduced 5x, kernel 4.26-4.48us):
//   - 128 CTAs x 256 threads, 2 points/thread via float4 LDG/STG
//     (1024 warps; float4 I/O worth ~0.4us over float2)
//   - weights staged in smem as interleaved (wx,wy) float2 pairs with a
//     SPREAD fill (1 pair/thread across all 8 warps; measured 0.5us faster
//     than few-warp vectorized fill -- parallel fill latency before the bar)
//   - smem gathers are conflict-free LDS.64 broadcasts (~600B working set;
//     measured 0.6us faster than scattered per-thread LDG gathers)
//   - branchless triangle select (no BSSY/BSYNC divergence)
// Kernel sits on the launch-overhead floor: <0.5us of actual memory/ALU work,
// remainder is T_ovh + wave ramp. All pipes <3%, DRAM ~1.5%. The harness adds
// a fixed ~2.2us graph-replay overhead.

__device__ __forceinline__ void eval_point(
    float px, float py, const float2* __restrict__ w, float& ox, float& oy)
{
    const float NTOL = -1e-10f;

    float fx = __fmul_rn(px, 16.0f);    // exact (power-of-2 scale)
    float fy = __fmul_rn(py, 16.0f);
    int i = (int)floorf(fx);
    int j = (int)floorf(fy);
    i = min(max(i, 0), 15);
    j = min(max(j, 0), 15);

    float u = __fsub_rn(fx, (float)i);  // exact (Sterbenz)
    float v = __fsub_rn(fy, (float)j);  // exact

    // reference-faithful inside tests (exact fp32)
    float P  = __fsub_rn(fx, fy);                 // fl(16px - 16py)
    float s1 = __fsub_rn(P, (float)(i - j));      // T1 s
    float t2 = -s1;                               // T2 t (bitwise)

    bool in1 = (s1 > NTOL) && (v > NTOL) && (__fadd_rn(s1, v) < 1.0f);
    bool in2 = (u  > NTOL) && (t2 > NTOL) && (__fadd_rn(u, t2) < 1.0f);

    // interior gridline points fail every strict bbox in the reference
    bool on_g = ((u == 0.0f) && (i > 0)) || ((v == 0.0f) && (j > 0));
    bool hit = (px >= 0.0f) && (px < 1.0f) && (py >= 0.0f) && (py < 1.0f) &&
               !on_g && (in1 || in2);

    // branchless triangle select (argmax tie -> T2, upper triangle)
    int v00 = i * 17 + j;
    float s  = in2 ? u : __fsub_rn(u, v);
    float t  = in2 ? __fsub_rn(v, u) : v;
    int  k1  = in2 ? (v00 + 18) : (v00 + 17);
    int  k2  = in2 ? (v00 + 1)  : (v00 + 18);
    float b0 = __fsub_rn(__fsub_rn(1.0f, s), t);

    float2 w0 = w[v00];
    float2 w1 = w[k1];
    float2 w2 = w[k2];

    float rx = __fadd_rn(__fadd_rn(__fmul_rn(b0, w0.x), __fmul_rn(s, w1.x)),
                         __fmul_rn(t, w2.x));
    float ry = __fadd_rn(__fadd_rn(__fmul_rn(b0, w0.y), __fmul_rn(s, w1.y)),
                         __fmul_rn(t, w2.y));
    ox = hit ? rx : 0.0f;
    oy = hit ? ry : 0.0f;
}

__global__ void __launch_bounds__(256)
p1_eval_kernel(const float4* __restrict__ pts4,
               const float*  __restrict__ wx,
               const float*  __restrict__ wy,
               float4* __restrict__ out4)
{
    __shared__ float2 wsh[289];

    int tid = threadIdx.x;
    int gid = blockIdx.x * blockDim.x + tid;

    // issue the (independent) point load first so its L2/DRAM trip overlaps
    // the smem weight fill below
    float4 pp = pts4[gid];   // two points: (x0,y0,x1,y1)

    // spread weight stage: 1 (wx,wy) pair per thread across all 8 warps,
    // 33-element tail predicated
    if (tid < 289)
        wsh[tid] = make_float2(wx[tid], wy[tid]);
    int t2i = tid + 256;
    if (t2i < 289)
        wsh[t2i] = make_float2(wx[t2i], wy[t2i]);
    __syncthreads();

    float4 r;
    eval_point(pp.x, pp.y, wsh, r.x, r.y);
    eval_point(pp.z, pp.w, wsh, r.z, r.w);

    out4[gid] = r;
}

extern "C" void kernel_launch(void* const* d_in, const int* in_sizes, int n_in,
                              void* d_out, int out_size)
{
    const float4* pts4 = (const float4*)d_in[0];
    const float*  wx   = (const float*)d_in[1];
    const float*  wy   = (const float*)d_in[2];
    float4* out4 = (float4*)d_out;

    // 65536 points -> 32768 float4 -> 128 blocks x 256 threads (one wave)
    int n4 = (in_sizes[0] / 2) / 2;
    int threads = 256;
    int blocks = n4 / threads;     // 128
    p1_eval_kernel<<<blocks, threads>>>(pts4, wx, wy, out4);
}

// round 15
// speedup vs baseline: 1.0615x; 1.0615x over previous
#include <cuda_runtime.h>

// P1 vector FEM eval on structured 16x16 triangulated unit square.
// Bit-faithful numerics (R4): exact fp32 classification, interior-gridline
// bbox exclusion, argmax tie -> upper triangle, reference op-order output.
//
// FINAL (converged optimum; harness 6.624us reproduced 6x, kernel 4.26-4.48us):
//   - 128 CTAs x 256 threads, 2 points/thread via float4 LDG/STG
//     (1024 warps; float4 I/O worth ~0.4us over float2)
//   - weights staged in smem as interleaved (wx,wy) float2 pairs with a
//     SPREAD fill (1 pair/thread across all 8 warps; measured 0.5us faster
//     than few-warp vectorized fill -- parallel fill latency before the bar)
//   - smem gathers are conflict-free LDS.64 broadcasts (~600B working set;
//     measured 0.6us faster than scattered per-thread LDG gathers)
//   - branchless triangle select (no BSSY/BSYNC divergence)
// Kernel sits on the launch-overhead floor: <0.5us of actual memory/ALU work,
// remainder is T_ovh + wave ramp. All pipes <3%, DRAM ~1.6%. The harness adds
// a fixed ~2.2us graph-replay overhead.

__device__ __forceinline__ void eval_point(
    float px, float py, const float2* __restrict__ w, float& ox, float& oy)
{
    const float NTOL = -1e-10f;

    float fx = __fmul_rn(px, 16.0f);    // exact (power-of-2 scale)
    float fy = __fmul_rn(py, 16.0f);
    int i = (int)floorf(fx);
    int j = (int)floorf(fy);
    i = min(max(i, 0), 15);
    j = min(max(j, 0), 15);

    float u = __fsub_rn(fx, (float)i);  // exact (Sterbenz)
    float v = __fsub_rn(fy, (float)j);  // exact

    // reference-faithful inside tests (exact fp32)
    float P  = __fsub_rn(fx, fy);                 // fl(16px - 16py)
    float s1 = __fsub_rn(P, (float)(i - j));      // T1 s
    float t2 = -s1;                               // T2 t (bitwise)

    bool in1 = (s1 > NTOL) && (v > NTOL) && (__fadd_rn(s1, v) < 1.0f);
    bool in2 = (u  > NTOL) && (t2 > NTOL) && (__fadd_rn(u, t2) < 1.0f);

    // interior gridline points fail every strict bbox in the reference
    bool on_g = ((u == 0.0f) && (i > 0)) || ((v == 0.0f) && (j > 0));
    bool hit = (px >= 0.0f) && (px < 1.0f) && (py >= 0.0f) && (py < 1.0f) &&
               !on_g && (in1 || in2);

    // branchless triangle select (argmax tie -> T2, upper triangle)
    int v00 = i * 17 + j;
    float s  = in2 ? u : __fsub_rn(u, v);
    float t  = in2 ? __fsub_rn(v, u) : v;
    int  k1  = in2 ? (v00 + 18) : (v00 + 17);
    int  k2  = in2 ? (v00 + 1)  : (v00 + 18);
    float b0 = __fsub_rn(__fsub_rn(1.0f, s), t);

    float2 w0 = w[v00];
    float2 w1 = w[k1];
    float2 w2 = w[k2];

    float rx = __fadd_rn(__fadd_rn(__fmul_rn(b0, w0.x), __fmul_rn(s, w1.x)),
                         __fmul_rn(t, w2.x));
    float ry = __fadd_rn(__fadd_rn(__fmul_rn(b0, w0.y), __fmul_rn(s, w1.y)),
                         __fmul_rn(t, w2.y));
    ox = hit ? rx : 0.0f;
    oy = hit ? ry : 0.0f;
}

__global__ void __launch_bounds__(256)
p1_eval_kernel(const float4* __restrict__ pts4,
               const float*  __restrict__ wx,
               const float*  __restrict__ wy,
               float4* __restrict__ out4)
{
    __shared__ float2 wsh[289];

    int tid = threadIdx.x;
    int gid = blockIdx.x * blockDim.x + tid;

    // issue the (independent) point load first so its L2/DRAM trip overlaps
    // the smem weight fill below
    float4 pp = pts4[gid];   // two points: (x0,y0,x1,y1)

    // spread weight stage: 1 (wx,wy) pair per thread across all 8 warps,
    // 33-element tail predicated
    if (tid < 289)
        wsh[tid] = make_float2(wx[tid], wy[tid]);
    int t2i = tid + 256;
    if (t2i < 289)
        wsh[t2i] = make_float2(wx[t2i], wy[t2i]);
    __syncthreads();

    float4 r;
    eval_point(pp.x, pp.y, wsh, r.x, r.y);
    eval_point(pp.z, pp.w, wsh, r.z, r.w);

    out4[gid] = r;
}

extern "C" void kernel_launch(void* const* d_in, const int* in_sizes, int n_in,
                              void* d_out, int out_size)
{
    const float4* pts4 = (const float4*)d_in[0];
    const float*  wx   = (const float*)d_in[1];
    const float*  wy   = (const float*)d_in[2];
    float4* out4 = (float4*)d_out;

    // 65536 points -> 32768 float4 -> 128 blocks x 256 threads (one wave)
    int n4 = (in_sizes[0] / 2) / 2;
    int threads = 256;
    int blocks = n4 / threads;     // 128
    p1_eval_kernel<<<blocks, threads>>>(pts4, wx, wy, out4);
}